// round 4
// baseline (speedup 1.0000x reference)
#include <cuda_runtime.h>

// MultiStageFIRFilter: y = x + sum_{a=1..20} xa_a,
//   xa_a[b,t] = (1/a) * sum_{k=0..24} mc[b,t,k] * xa_{a-1}[b,t-k]  (xa_0 = x, causal)
//
// Fused halo-recompute kernel. R=4 positions/thread, 256 threads/block,
// float4 shared traffic, 8 independent FMA chains per thread, stage trim.

#define NB      4
#define NT      16384
#define M       25
#define STAGES  20
#define HALO    480       // STAGES * (M-1)
#define THREADS 256
#define R       4
#define EXT     1024      // THREADS * R
#define TILE    544       // EXT - HALO
#define PAD     24
#define NTILES  31        // ceil(16384 / 544)

__global__ __launch_bounds__(THREADS, 1)
void fir_kernel(const float* __restrict__ x, const float* __restrict__ mc,
                float* __restrict__ out)
{
    __shared__ __align__(16) float s0[PAD + EXT];
    __shared__ __align__(16) float s1[PAD + EXT];

    const int tile = blockIdx.x % NTILES;
    const int b    = blockIdx.x / NTILES;
    const int t0   = tile * TILE;
    const int tid  = threadIdx.x;
    const int i0   = R * tid;              // local position (multiple of 4)
    const int p0   = t0 - HALO + i0;       // global time of first owned position
    const size_t rowbase = (size_t)b * NT;

    if (tid < PAD) { s0[tid] = 0.0f; s1[tid] = 0.0f; }

    // ---- per-position coefficients in registers: c[25*r + k] = mc[p0+r][k] ----
    // The 100 floats starting at row p0 are contiguous AND already row-major [r][k].
    float c[100];
    if (p0 >= 0 && p0 + R - 1 < NT) {
        const float4* g = (const float4*)(mc + (rowbase + (size_t)p0) * M);  // 16B-aligned (p0%4==0)
        #pragma unroll
        for (int k = 0; k < 25; k++) {
            float4 v = g[k];
            c[4*k] = v.x; c[4*k+1] = v.y; c[4*k+2] = v.z; c[4*k+3] = v.w;
        }
    } else {
        #pragma unroll
        for (int r = 0; r < R; r++) {
            const int p = p0 + r;
            if (p >= 0 && p < NT) {
                const float* g = mc + (rowbase + (size_t)p) * M;
                #pragma unroll
                for (int k = 0; k < 25; k++) c[25*r + k] = g[k];
            } else {
                #pragma unroll
                for (int k = 0; k < 25; k++) c[25*r + k] = 0.0f;
            }
        }
    }

    // ---- stage 0: xa = x ----
    float v[R], y[R];
    if (p0 >= 0 && p0 + R - 1 < NT) {
        const float4 xv = *(const float4*)(x + rowbase + p0);
        v[0] = xv.x; v[1] = xv.y; v[2] = xv.z; v[3] = xv.w;
    } else {
        #pragma unroll
        for (int r = 0; r < R; r++) {
            const int p = p0 + r;
            v[r] = (p >= 0 && p < NT) ? x[rowbase + p] : 0.0f;
        }
    }
    #pragma unroll
    for (int r = 0; r < R; r++) y[r] = v[r];

    *((float4*)(s0 + PAD + i0)) = make_float4(v[0], v[1], v[2], v[3]);
    __syncthreads();

    float* cur = s0;
    float* nxt = s1;
    const bool ghost = (p0 < 0);   // t<0 positions: xa stays exactly 0 (tile 0 only)

    #pragma unroll
    for (int a = 1; a <= STAGES; a++) {
        const float inv = 1.0f / (float)a;         // compile-time constant
        if (tid >= 6 * a) {                        // exactness trim: need pos >= 24a
            // w[j] = xa_{a-1}[position i0-24+j], j = 0..23.
            // Position q lives at smem index PAD + q, so position i0-24 is at
            // cur + PAD + i0 - 24 = cur + i0.  (16B-aligned: i0 % 4 == 0)
            float w[24];
            const float4* wp = (const float4*)(cur + i0);
            #pragma unroll
            for (int j = 0; j < 6; j++) {
                float4 q = wp[j];
                w[4*j] = q.x; w[4*j+1] = q.y; w[4*j+2] = q.z; w[4*j+3] = q.w;
            }

            // val(i0 + d) for d in [-24, 3]: d < 0 -> w[24+d], d >= 0 -> v[d]
            float acc[R];
            #pragma unroll
            for (int r = 0; r < R; r++) {
                float pA = 0.0f, pB = 0.0f;        // two independent chains
                #pragma unroll
                for (int k = 0; k <= 12; k++) {
                    const int d = r - k;
                    const float val = (d >= 0) ? v[d] : w[24 + d];
                    pA = fmaf(c[25*r + k], val, pA);
                }
                #pragma unroll
                for (int k = 13; k <= 24; k++) {
                    const int d = r - k;
                    pB = fmaf(c[25*r + k], w[24 + d], pB);
                }
                acc[r] = (pA + pB) * inv;
            }
            if (ghost) {
                #pragma unroll
                for (int r = 0; r < R; r++) acc[r] = 0.0f;
            }
            #pragma unroll
            for (int r = 0; r < R; r++) { y[r] += acc[r]; v[r] = acc[r]; }
            *((float4*)(nxt + PAD + i0)) = make_float4(v[0], v[1], v[2], v[3]);
        }
        __syncthreads();
        float* tmp = cur; cur = nxt; nxt = tmp;
    }

    // ---- write owned (non-halo) outputs ----
    if (i0 >= HALO && p0 < NT) {
        if (p0 + R - 1 < NT) {
            *((float4*)(out + rowbase + p0)) = make_float4(y[0], y[1], y[2], y[3]);
        } else {
            #pragma unroll
            for (int r = 0; r < R; r++)
                if (p0 + r < NT) out[rowbase + p0 + r] = y[r];
        }
    }
}

extern "C" void kernel_launch(void* const* d_in, const int* in_sizes, int n_in,
                              void* d_out, int out_size)
{
    const float* x  = (const float*)d_in[0];   // (4, 16384) float32
    const float* mc = (const float*)d_in[1];   // (4, 16384, 25) float32
    float* out = (float*)d_out;                // (4, 16384) float32
    fir_kernel<<<NB * NTILES, THREADS>>>(x, mc, out);
}